// round 7
// baseline (speedup 1.0000x reference)
#include <cuda_runtime.h>

// Problem constants (fixed by the reference).
#define BATCH 512
#define LSEQ  24576
#define LP    8192        // LSEQ / 3
#define HID   10

// Scratch for conv output (16 MB + pad for the prefetch overread).
__device__ float g_conv[(size_t)BATCH * LP + 4];

// ---------------------------------------------------------------------------
// Kernel 1: conv1d k=3 stride=3 + bias + relu.
// ---------------------------------------------------------------------------
__global__ void conv_kernel(const float* __restrict__ x,
                            const float* __restrict__ cw,
                            const float* __restrict__ cb) {
    int idx = blockIdx.x * blockDim.x + threadIdx.x;   // 0 .. 512*2048-1
    int b = idx >> 11;          // 2048 quads per batch row
    int i = idx & 2047;
    if (b >= BATCH) return;

    const float4* xp = reinterpret_cast<const float4*>(x + (size_t)b * LSEQ + 12 * i);
    float4 a = xp[0];
    float4 m = xp[1];
    float4 c = xp[2];

    float w0 = cw[0], w1 = cw[1], w2 = cw[2], b0 = cb[0];

    float o0 = fmaf(a.x, w0, fmaf(a.y, w1, fmaf(a.z, w2, b0)));
    float o1 = fmaf(a.w, w0, fmaf(m.x, w1, fmaf(m.y, w2, b0)));
    float o2 = fmaf(m.z, w0, fmaf(m.w, w1, fmaf(c.x, w2, b0)));
    float o3 = fmaf(c.y, w0, fmaf(c.z, w1, fmaf(c.w, w2, b0)));

    float4 o;
    o.x = fmaxf(o0, 0.0f);
    o.y = fmaxf(o1, 0.0f);
    o.z = fmaxf(o2, 0.0f);
    o.w = fmaxf(o3, 0.0f);
    *reinterpret_cast<float4*>(g_conv + (size_t)b * LP + 4 * i) = o;
}

// ---------------------------------------------------------------------------
// Packed f32x2 + MUFU helpers.
// ---------------------------------------------------------------------------
typedef unsigned long long u64;

__device__ __forceinline__ u64 dup2(float x) {
    u64 r;
    asm("mov.b64 %0, {%1, %1};" : "=l"(r) : "f"(x));
    return r;
}
__device__ __forceinline__ u64 pack2(float lo, float hi) {
    u64 r;
    asm("mov.b64 %0, {%1, %2};" : "=l"(r) : "f"(lo), "f"(hi));
    return r;
}
__device__ __forceinline__ u64 ffma2(u64 a, u64 b, u64 c) {
    u64 d;
    asm("fma.rn.f32x2 %0, %1, %2, %3;" : "=l"(d) : "l"(a), "l"(b), "l"(c));
    return d;
}
__device__ __forceinline__ float hsum2(u64 v) {
    float lo, hi;
    asm("mov.b64 {%0, %1}, %2;" : "=f"(lo), "=f"(hi) : "l"(v));
    return lo + hi;
}
__device__ __forceinline__ float tanh_apx(float x) {
    float y;
    asm("tanh.approx.f32 %0, %1;" : "=f"(y) : "f"(x));
    return y;
}

// Shared-memory broadcast helpers: h vector read back as packed 64-bit pairs.
__device__ __forceinline__ void sts_f32(unsigned addr, float v) {
    asm volatile("st.shared.f32 [%0], %1;" :: "r"(addr), "f"(v) : "memory");
}
__device__ __forceinline__ void lds_v2u64(unsigned addr, u64& a, u64& b) {
    asm volatile("ld.shared.v2.u64 {%0,%1}, [%2];"
                 : "=l"(a), "=l"(b) : "r"(addr) : "memory");
}
__device__ __forceinline__ u64 lds_u64(unsigned addr) {
    u64 a;
    asm volatile("ld.shared.u64 %0, [%1];" : "=l"(a) : "r"(addr) : "memory");
    return a;
}
__device__ __forceinline__ void lds_v2f(unsigned addr, float& a, float& b) {
    asm volatile("ld.shared.v2.f32 {%0,%1}, [%2];"
                 : "=f"(a), "=f"(b) : "r"(addr) : "memory");
}

// ---------------------------------------------------------------------------
// Kernel 2: LSTM scan + final MLP.
// Lane j<10 of a 16-lane segment owns hidden unit j. Gate dots via FFMA2 over
// k-pairs. Chains are laid out as COMPLETE per-gate blocks in consumption
// order (g, i, f, o), each tanh issued right after its gate's hsum, so the
// MUFU for g starts ~16 cyc earlier and the f/o chains overlap in-flight
// MUFUs instead of delaying them.
// ---------------------------------------------------------------------------
__global__ void __launch_bounds__(128, 1)
lstm_kernel(const float* __restrict__ w_ih,
            const float* __restrict__ w_hh,
            const float* __restrict__ b_ih,
            const float* __restrict__ b_hh,
            const float* __restrict__ mlp_w,
            const float* __restrict__ mlp_b,
            float* __restrict__ out) {
    __shared__ __align__(16) float hbuf[8 * 16];   // 8 segments * 16 slots

    int tid = blockIdx.x * blockDim.x + threadIdx.x;
    int grp = tid >> 4;                 // batch element, 0..511
    int j   = tid & 15;                 // lane within segment
    int jc  = j < HID ? j : HID - 1;    // clamp idle lanes onto valid rows
    if (grp >= BATCH) return;

    int seg = (threadIdx.x >> 4);       // segment within block, 0..7
    unsigned sbase = (unsigned)__cvta_generic_to_shared(&hbuf[seg * 16]);
    unsigned smy   = sbase + 4u * (unsigned)j;

    // Recurrent weights packed over k-pairs (torch gate order i,f,g,o).
    // Sigmoid-gate weights pre-scaled by 0.5 (sigmoid via tanh identity).
    u64 wi2[5], wf2[5], wg2[5], wo2[5];
#pragma unroll
    for (int p = 0; p < 5; p++) {
        wi2[p] = pack2(0.5f * w_hh[(0 * HID + jc) * HID + 2 * p],
                       0.5f * w_hh[(0 * HID + jc) * HID + 2 * p + 1]);
        wf2[p] = pack2(0.5f * w_hh[(1 * HID + jc) * HID + 2 * p],
                       0.5f * w_hh[(1 * HID + jc) * HID + 2 * p + 1]);
        wg2[p] = pack2(       w_hh[(2 * HID + jc) * HID + 2 * p],
                              w_hh[(2 * HID + jc) * HID + 2 * p + 1]);
        wo2[p] = pack2(0.5f * w_hh[(3 * HID + jc) * HID + 2 * p],
                       0.5f * w_hh[(3 * HID + jc) * HID + 2 * p + 1]);
    }
    // Input weight + bias packed into (value, 0): seeded via one FFMA2 each.
    u64 wxi2 = pack2(0.5f * w_ih[0 * HID + jc], 0.0f);
    u64 wxf2 = pack2(0.5f * w_ih[1 * HID + jc], 0.0f);
    u64 wxg2 = pack2(       w_ih[2 * HID + jc], 0.0f);
    u64 wxo2 = pack2(0.5f * w_ih[3 * HID + jc], 0.0f);
    u64 bbi2 = pack2(0.5f * (b_ih[0 * HID + jc] + b_hh[0 * HID + jc]), 0.0f);
    u64 bbf2 = pack2(0.5f * (b_ih[1 * HID + jc] + b_hh[1 * HID + jc]), 0.0f);
    u64 bbg2 = pack2(       (b_ih[2 * HID + jc] + b_hh[2 * HID + jc]), 0.0f);
    u64 bbo2 = pack2(0.5f * (b_ih[3 * HID + jc] + b_hh[3 * HID + jc]), 0.0f);

    float cst = 0.0f;
    float hcst = 0.0f;                  // 0.5 * cst, maintained each step

    // Seed h = 0 in smem.
    sts_f32(smy, 0.0f);

    const float* convp = g_conv + (size_t)grp * LP;
    float4 cur = *reinterpret_cast<const float4*>(convp);

    for (int t4 = 0; t4 < LP / 4; t4++) {
        // Prefetch next quad (padded overread on the last iteration).
        float4 nxt = *reinterpret_cast<const float4*>(convp + 4 * t4 + 4);

        float cts[4] = {cur.x, cur.y, cur.z, cur.w};
#pragma unroll
        for (int u = 0; u < 4; u++) {
            u64 ct2 = dup2(cts[u]);     // off critical path (ct known early)

            // Broadcast previous h as packed pairs (smem broadcast reads).
            u64 h01, h23, h45, h67, h89;
            lds_v2u64(sbase, h01, h23);
            lds_v2u64(sbase + 16u, h45, h67);
            h89 = lds_u64(sbase + 32u);

            // Seeds (independent of h; scheduled into the LDS shadow).
            u64 sg = ffma2(wxg2, ct2, bbg2);
            u64 si = ffma2(wxi2, ct2, bbi2);
            u64 sf = ffma2(wxf2, ct2, bbf2);
            u64 so = ffma2(wxo2, ct2, bbo2);

            // --- g gate: full chain, hsum, tanh issued immediately ---
            u64 ag2 = ffma2(wg2[0], h01, sg);
            ag2 = ffma2(wg2[1], h23, ag2);
            ag2 = ffma2(wg2[2], h45, ag2);
            ag2 = ffma2(wg2[3], h67, ag2);
            ag2 = ffma2(wg2[4], h89, ag2);
            float gg = tanh_apx(hsum2(ag2));
            float hgg = 0.5f * gg;

            // --- i gate ---
            u64 ai2 = ffma2(wi2[0], h01, si);
            ai2 = ffma2(wi2[1], h23, ai2);
            ai2 = ffma2(wi2[2], h45, ai2);
            ai2 = ffma2(wi2[3], h67, ai2);
            ai2 = ffma2(wi2[4], h89, ai2);
            float ti = tanh_apx(hsum2(ai2));

            // --- f gate ---
            u64 af2 = ffma2(wf2[0], h01, sf);
            af2 = ffma2(wf2[1], h23, af2);
            af2 = ffma2(wf2[2], h45, af2);
            af2 = ffma2(wf2[3], h67, af2);
            af2 = ffma2(wf2[4], h89, af2);
            float tf = tanh_apx(hsum2(af2));

            // c' = sig(f)*c + sig(i)*g with sig(x)=0.5*t+0.5 folded:
            //   P = 0.5*gg*ti + 0.5*gg ; Q = 0.5*c + P ; c' = fma(0.5*c, tf, Q)
            float P = fmaf(hgg, ti, hgg);
            float Q = hcst + P;
            cst = fmaf(hcst, tf, Q);
            hcst = 0.5f * cst;
            float tcst = tanh_apx(cst);

            // --- o gate (result needed only at the final h-mul) ---
            u64 ao2 = ffma2(wo2[0], h01, so);
            ao2 = ffma2(wo2[1], h23, ao2);
            ao2 = ffma2(wo2[2], h45, ao2);
            ao2 = ffma2(wo2[3], h67, ao2);
            ao2 = ffma2(wo2[4], h89, ao2);
            float to = tanh_apx(hsum2(ao2));
            float og = fmaf(to, 0.5f, 0.5f);

            float h = og * tcst;

            // Publish new h for the next step.
            sts_f32(smy, h);
        }
        cur = nxt;
    }

    // Final MLP: read h_0..h_9 from smem; lanes 0..2 emit the 3 outputs.
    if (j < 3) {
        float h0, h1, h2, h3, h4, h5, h6, h7, h8, h9;
        lds_v2f(sbase,       h0, h1);
        lds_v2f(sbase + 8u,  h2, h3);
        lds_v2f(sbase + 16u, h4, h5);
        lds_v2f(sbase + 24u, h6, h7);
        lds_v2f(sbase + 32u, h8, h9);
        const float* mw = mlp_w + j * HID;
        float acc = mlp_b[j];
        acc = fmaf(mw[0], h0, acc);
        acc = fmaf(mw[1], h1, acc);
        acc = fmaf(mw[2], h2, acc);
        acc = fmaf(mw[3], h3, acc);
        acc = fmaf(mw[4], h4, acc);
        acc = fmaf(mw[5], h5, acc);
        acc = fmaf(mw[6], h6, acc);
        acc = fmaf(mw[7], h7, acc);
        acc = fmaf(mw[8], h8, acc);
        acc = fmaf(mw[9], h9, acc);
        out[grp * 3 + j] = acc;
    }
}

// ---------------------------------------------------------------------------
extern "C" void kernel_launch(void* const* d_in, const int* in_sizes, int n_in,
                              void* d_out, int out_size) {
    const float* x      = (const float*)d_in[0];
    const float* conv_w = (const float*)d_in[1];
    const float* conv_b = (const float*)d_in[2];
    const float* w_ih   = (const float*)d_in[3];
    const float* w_hh   = (const float*)d_in[4];
    const float* b_ih   = (const float*)d_in[5];
    const float* b_hh   = (const float*)d_in[6];
    const float* mlp_w  = (const float*)d_in[7];
    const float* mlp_b  = (const float*)d_in[8];
    float* out = (float*)d_out;

    // Conv: 512*2048 threads, 4 outputs each.
    {
        int total = BATCH * (LP / 4);
        int threads = 256;
        int blocks = (total + threads - 1) / threads;
        conv_kernel<<<blocks, threads>>>(x, conv_w, conv_b);
    }
    // LSTM: 512 groups * 16 lanes = 8192 threads (64 blocks x 128).
    {
        int threads = 128;
        int blocks = (BATCH * 16) / threads;   // 64
        lstm_kernel<<<blocks, threads>>>(w_ih, w_hh, b_ih, b_hh, mlp_w, mlp_b, out);
    }
}

// round 8
// speedup vs baseline: 1.0131x; 1.0131x over previous
#include <cuda_runtime.h>

// Problem constants (fixed by the reference).
#define BATCH 512
#define LSEQ  24576
#define LP    8192        // LSEQ / 3
#define HID   10

// Scratch for conv output (16 MB + pad for the prefetch overread).
__device__ float g_conv[(size_t)BATCH * LP + 4];

// ---------------------------------------------------------------------------
// Kernel 1: conv1d k=3 stride=3 + bias + relu.
// ---------------------------------------------------------------------------
__global__ void conv_kernel(const float* __restrict__ x,
                            const float* __restrict__ cw,
                            const float* __restrict__ cb) {
    int idx = blockIdx.x * blockDim.x + threadIdx.x;   // 0 .. 512*2048-1
    int b = idx >> 11;          // 2048 quads per batch row
    int i = idx & 2047;
    if (b >= BATCH) return;

    const float4* xp = reinterpret_cast<const float4*>(x + (size_t)b * LSEQ + 12 * i);
    float4 a = xp[0];
    float4 m = xp[1];
    float4 c = xp[2];

    float w0 = cw[0], w1 = cw[1], w2 = cw[2], b0 = cb[0];

    float o0 = fmaf(a.x, w0, fmaf(a.y, w1, fmaf(a.z, w2, b0)));
    float o1 = fmaf(a.w, w0, fmaf(m.x, w1, fmaf(m.y, w2, b0)));
    float o2 = fmaf(m.z, w0, fmaf(m.w, w1, fmaf(c.x, w2, b0)));
    float o3 = fmaf(c.y, w0, fmaf(c.z, w1, fmaf(c.w, w2, b0)));

    float4 o;
    o.x = fmaxf(o0, 0.0f);
    o.y = fmaxf(o1, 0.0f);
    o.z = fmaxf(o2, 0.0f);
    o.w = fmaxf(o3, 0.0f);
    *reinterpret_cast<float4*>(g_conv + (size_t)b * LP + 4 * i) = o;
}

// ---------------------------------------------------------------------------
// Packed f32x2 + MUFU helpers.
// ---------------------------------------------------------------------------
typedef unsigned long long u64;

__device__ __forceinline__ u64 dup2(float x) {
    u64 r;
    asm("mov.b64 %0, {%1, %1};" : "=l"(r) : "f"(x));
    return r;
}
__device__ __forceinline__ u64 pack2(float lo, float hi) {
    u64 r;
    asm("mov.b64 %0, {%1, %2};" : "=l"(r) : "f"(lo), "f"(hi));
    return r;
}
__device__ __forceinline__ u64 ffma2(u64 a, u64 b, u64 c) {
    u64 d;
    asm("fma.rn.f32x2 %0, %1, %2, %3;" : "=l"(d) : "l"(a), "l"(b), "l"(c));
    return d;
}
__device__ __forceinline__ float hsum2(u64 v) {
    float lo, hi;
    asm("mov.b64 {%0, %1}, %2;" : "=f"(lo), "=f"(hi) : "l"(v));
    return lo + hi;
}
__device__ __forceinline__ float tanh_apx(float x) {
    float y;
    asm("tanh.approx.f32 %0, %1;" : "=f"(y) : "f"(x));
    return y;
}

// Shared-memory broadcast helpers.
__device__ __forceinline__ void sts_f32(unsigned addr, float v) {
    asm volatile("st.shared.f32 [%0], %1;" :: "r"(addr), "f"(v) : "memory");
}
__device__ __forceinline__ void lds_v2u64(unsigned addr, u64& a, u64& b) {
    asm volatile("ld.shared.v2.u64 {%0,%1}, [%2];"
                 : "=l"(a), "=l"(b) : "r"(addr) : "memory");
}
__device__ __forceinline__ u64 lds_u64(unsigned addr) {
    u64 a;
    asm volatile("ld.shared.u64 %0, [%1];" : "=l"(a) : "r"(addr) : "memory");
    return a;
}
__device__ __forceinline__ void lds_v2f(unsigned addr, float& a, float& b) {
    asm volatile("ld.shared.v2.f32 {%0,%1}, [%2];"
                 : "=f"(a), "=f"(b) : "r"(addr) : "memory");
}

// ---------------------------------------------------------------------------
// Kernel 2: LSTM scan + final MLP.
// ONE WARP (32 lanes) per batch element. Half A (lanes 0-15): gates i,g of
// hidden unit j = lane&15. Half B (lanes 16-31): gates f,o of unit j.
// Each lane: 2 FFMA2 chains + 3 MUFUs per step (vs 4 chains + 5 MUFUs before)
// -> FMA issue pressure halved. The halves recombine with ONE shfl_xor(16):
// A sends P = sig(i)*tanh(g) (local to A), B sends tf; both halves then
// redundantly (and bit-identically) compute cst and tanh(cst); half B forms
// h = og*tanh(cst) and predicated-stores it.
// ---------------------------------------------------------------------------
__global__ void __launch_bounds__(128, 1)
lstm_kernel(const float* __restrict__ w_ih,
            const float* __restrict__ w_hh,
            const float* __restrict__ b_ih,
            const float* __restrict__ b_hh,
            const float* __restrict__ mlp_w,
            const float* __restrict__ mlp_b,
            float* __restrict__ out) {
    __shared__ __align__(16) float hbuf[4 * 16];   // 4 warps/block * 16 slots

    int tid  = blockIdx.x * blockDim.x + threadIdx.x;
    int grp  = tid >> 5;                // batch element, 0..511
    int lane = tid & 31;
    int half = lane >> 4;               // 0 = (i,g) half, 1 = (f,o) half
    int j    = lane & 15;
    int jc   = j < HID ? j : HID - 1;   // clamp idle lanes onto valid rows
    if (grp >= BATCH) return;

    int seg = (threadIdx.x >> 5);       // warp within block, 0..3
    unsigned sbase = (unsigned)__cvta_generic_to_shared(&hbuf[seg * 16]);
    unsigned smy   = sbase + 4u * (unsigned)j;

    // Gate rows for this half (torch order i,f,g,o):
    //   half A: gate1 = i (row 0), gate2 = g (row 2)
    //   half B: gate1 = f (row 1), gate2 = o (row 3)
    // gate1 is always sigmoid (scale 0.5); gate2 is tanh for A (scale 1),
    // sigmoid for B (scale 0.5).
    int g1 = half ? 1 : 0;
    int g2 = half ? 3 : 2;
    float s2 = half ? 0.5f : 1.0f;

    u64 w1_2[5], w2_2[5];
#pragma unroll
    for (int p = 0; p < 5; p++) {
        w1_2[p] = pack2(0.5f * w_hh[(g1 * HID + jc) * HID + 2 * p],
                        0.5f * w_hh[(g1 * HID + jc) * HID + 2 * p + 1]);
        w2_2[p] = pack2(s2 * w_hh[(g2 * HID + jc) * HID + 2 * p],
                        s2 * w_hh[(g2 * HID + jc) * HID + 2 * p + 1]);
    }
    u64 wx1 = pack2(0.5f * w_ih[g1 * HID + jc], 0.0f);
    u64 wx2 = pack2(s2 * w_ih[g2 * HID + jc], 0.0f);
    u64 bb1 = pack2(0.5f * (b_ih[g1 * HID + jc] + b_hh[g1 * HID + jc]), 0.0f);
    u64 bb2 = pack2(s2 * (b_ih[g2 * HID + jc] + b_hh[g2 * HID + jc]), 0.0f);

    float cst = 0.0f;
    float hcst = 0.0f;                  // 0.5 * cst, maintained each step
    bool isB = (half == 1);

    // Seed h = 0 in smem (half B owns the slots).
    if (isB) sts_f32(smy, 0.0f);
    __syncwarp();

    const float* convp = g_conv + (size_t)grp * LP;
    float4 cur = *reinterpret_cast<const float4*>(convp);

    for (int t4 = 0; t4 < LP / 4; t4++) {
        // Prefetch next quad (padded overread on the last iteration).
        float4 nxt = *reinterpret_cast<const float4*>(convp + 4 * t4 + 4);

        float cts[4] = {cur.x, cur.y, cur.z, cur.w};
#pragma unroll
        for (int u = 0; u < 4; u++) {
            u64 ct2 = dup2(cts[u]);     // off critical path

            // Broadcast previous h as packed pairs (smem broadcast reads).
            u64 h01, h23, h45, h67, h89;
            lds_v2u64(sbase, h01, h23);
            lds_v2u64(sbase + 16u, h45, h67);
            h89 = lds_u64(sbase + 32u);

            // Seeds (independent of h).
            u64 a1 = ffma2(wx1, ct2, bb1);
            u64 a2 = ffma2(wx2, ct2, bb2);

            // Two 5-deep chains, interleaved.
            a1 = ffma2(w1_2[0], h01, a1);
            a2 = ffma2(w2_2[0], h01, a2);
            a1 = ffma2(w1_2[1], h23, a1);
            a2 = ffma2(w2_2[1], h23, a2);
            a1 = ffma2(w1_2[2], h45, a1);
            a2 = ffma2(w2_2[2], h45, a2);
            a1 = ffma2(w1_2[3], h67, a1);
            a2 = ffma2(w2_2[3], h67, a2);
            a1 = ffma2(w1_2[4], h89, a1);
            a2 = ffma2(w2_2[4], h89, a2);

            // t1 = A: tanh(0.5*pre_i) | B: tanh(0.5*pre_f)
            // t2 = A: tanh(pre_g)     | B: tanh(0.5*pre_o)
            float t2 = tanh_apx(hsum2(a2));
            float t1 = tanh_apx(hsum2(a1));

            // Half A forms P = sig(i)*tanh(g) = 0.5*t2*t1 + 0.5*t2.
            // (In half B this value is unused garbage but finite.)
            float ht2 = 0.5f * t2;
            float Ploc = fmaf(ht2, t1, ht2);

            // Butterfly: A sends P, B sends tf (= t1).
            float xval = isB ? t1 : Ploc;
            float other = __shfl_xor_sync(0xffffffffu, xval, 16, 32);

            float Pv  = isB ? other : Ploc;
            float tfv = isB ? t1 : other;

            // cst' = sig(f)*cst + P, with sig folded: fma(hcst, tf, hcst + P).
            // Both halves compute identically -> stay bit-synchronized.
            float Q = hcst + Pv;
            cst = fmaf(hcst, tfv, Q);
            hcst = 0.5f * cst;
            float tcst = tanh_apx(cst);

            // Half B: og = sig(o) = 0.5*t2 + 0.5 ; h = og * tanh(cst).
            float og = fmaf(t2, 0.5f, 0.5f);
            float h = og * tcst;

            if (isB) sts_f32(smy, h);
        }
        cur = nxt;
    }

    // Final MLP: read h_0..h_9 from smem; lanes 0..2 emit the 3 outputs.
    // (Same-warp program order: all half-B stores precede these loads.)
    __syncwarp();
    if (lane < 3) {
        float h0, h1, h2, h3, h4, h5, h6, h7, h8, h9;
        lds_v2f(sbase,       h0, h1);
        lds_v2f(sbase + 8u,  h2, h3);
        lds_v2f(sbase + 16u, h4, h5);
        lds_v2f(sbase + 24u, h6, h7);
        lds_v2f(sbase + 32u, h8, h9);
        const float* mw = mlp_w + lane * HID;
        float acc = mlp_b[lane];
        acc = fmaf(mw[0], h0, acc);
        acc = fmaf(mw[1], h1, acc);
        acc = fmaf(mw[2], h2, acc);
        acc = fmaf(mw[3], h3, acc);
        acc = fmaf(mw[4], h4, acc);
        acc = fmaf(mw[5], h5, acc);
        acc = fmaf(mw[6], h6, acc);
        acc = fmaf(mw[7], h7, acc);
        acc = fmaf(mw[8], h8, acc);
        acc = fmaf(mw[9], h9, acc);
        out[grp * 3 + lane] = acc;
    }
}

// ---------------------------------------------------------------------------
extern "C" void kernel_launch(void* const* d_in, const int* in_sizes, int n_in,
                              void* d_out, int out_size) {
    const float* x      = (const float*)d_in[0];
    const float* conv_w = (const float*)d_in[1];
    const float* conv_b = (const float*)d_in[2];
    const float* w_ih   = (const float*)d_in[3];
    const float* w_hh   = (const float*)d_in[4];
    const float* b_ih   = (const float*)d_in[5];
    const float* b_hh   = (const float*)d_in[6];
    const float* mlp_w  = (const float*)d_in[7];
    const float* mlp_b  = (const float*)d_in[8];
    float* out = (float*)d_out;

    // Conv: 512*2048 threads, 4 outputs each.
    {
        int total = BATCH * (LP / 4);
        int threads = 256;
        int blocks = (total + threads - 1) / threads;
        conv_kernel<<<blocks, threads>>>(x, conv_w, conv_b);
    }
    // LSTM: 512 batches * 32 lanes = 16384 threads (128 blocks x 128).
    {
        int threads = 128;
        int blocks = (BATCH * 32) / threads;   // 128
        lstm_kernel<<<blocks, threads>>>(w_ih, w_hh, b_ih, b_hh, mlp_w, mlp_b, out);
    }
}

// round 9
// speedup vs baseline: 1.0722x; 1.0583x over previous
#include <cuda_runtime.h>

// Problem constants (fixed by the reference).
#define BATCH 512
#define LSEQ  24576
#define LP    8192        // LSEQ / 3
#define HID   10

// ---------------------------------------------------------------------------
// Packed f32x2 + MUFU helpers.
// ---------------------------------------------------------------------------
typedef unsigned long long u64;

__device__ __forceinline__ u64 dup2(float x) {
    u64 r;
    asm("mov.b64 %0, {%1, %1};" : "=l"(r) : "f"(x));
    return r;
}
__device__ __forceinline__ u64 pack2(float lo, float hi) {
    u64 r;
    asm("mov.b64 %0, {%1, %2};" : "=l"(r) : "f"(lo), "f"(hi));
    return r;
}
__device__ __forceinline__ u64 ffma2(u64 a, u64 b, u64 c) {
    u64 d;
    asm("fma.rn.f32x2 %0, %1, %2, %3;" : "=l"(d) : "l"(a), "l"(b), "l"(c));
    return d;
}
__device__ __forceinline__ float hsum2(u64 v) {
    float lo, hi;
    asm("mov.b64 {%0, %1}, %2;" : "=f"(lo), "=f"(hi) : "l"(v));
    return lo + hi;
}
__device__ __forceinline__ float tanh_apx(float x) {
    float y;
    asm("tanh.approx.f32 %0, %1;" : "=f"(y) : "f"(x));
    return y;
}

// Shared-memory broadcast helpers: h vector read back as packed 64-bit pairs.
__device__ __forceinline__ void sts_f32(unsigned addr, float v) {
    asm volatile("st.shared.f32 [%0], %1;" :: "r"(addr), "f"(v) : "memory");
}
__device__ __forceinline__ void lds_v2u64(unsigned addr, u64& a, u64& b) {
    asm volatile("ld.shared.v2.u64 {%0,%1}, [%2];"
                 : "=l"(a), "=l"(b) : "r"(addr) : "memory");
}
__device__ __forceinline__ u64 lds_u64(unsigned addr) {
    u64 a;
    asm volatile("ld.shared.u64 %0, [%1];" : "=l"(a) : "r"(addr) : "memory");
    return a;
}
__device__ __forceinline__ void lds_v2f(unsigned addr, float& a, float& b) {
    asm volatile("ld.shared.v2.f32 {%0,%1}, [%2];"
                 : "=f"(a), "=f"(b) : "r"(addr) : "memory");
}

// ---------------------------------------------------------------------------
// Fused kernel: conv1d(k=3,s=3)+relu computed inline (in the recurrence's
// latency shadow, one chunk ahead) + LSTM scan + final MLP.
// Lane j<10 of a 16-lane segment owns hidden unit j. Gate dots via FFMA2 over
// k-pairs (R5 body — measured best). h broadcast via smem packed-pair reads.
// ---------------------------------------------------------------------------
__global__ void __launch_bounds__(128, 1)
lstm_kernel(const float* __restrict__ x,
            const float* __restrict__ cw,
            const float* __restrict__ cb,
            const float* __restrict__ w_ih,
            const float* __restrict__ w_hh,
            const float* __restrict__ b_ih,
            const float* __restrict__ b_hh,
            const float* __restrict__ mlp_w,
            const float* __restrict__ mlp_b,
            float* __restrict__ out) {
    __shared__ __align__(16) float hbuf[8 * 16];   // 8 segments * 16 slots

    int tid = blockIdx.x * blockDim.x + threadIdx.x;
    int grp = tid >> 4;                 // batch element, 0..511
    int j   = tid & 15;                 // lane within segment
    int jc  = j < HID ? j : HID - 1;    // clamp idle lanes onto valid rows
    if (grp >= BATCH) return;

    int seg = (threadIdx.x >> 4);       // segment within block, 0..7
    unsigned sbase = (unsigned)__cvta_generic_to_shared(&hbuf[seg * 16]);
    unsigned smy   = sbase + 4u * (unsigned)j;

    // Conv weights.
    float cw0 = cw[0], cw1 = cw[1], cw2 = cw[2], cb0 = cb[0];

    // Recurrent weights packed over k-pairs (torch gate order i,f,g,o).
    // Sigmoid-gate weights pre-scaled by 0.5 (sigmoid via tanh identity).
    u64 wi2[5], wf2[5], wg2[5], wo2[5];
#pragma unroll
    for (int p = 0; p < 5; p++) {
        wi2[p] = pack2(0.5f * w_hh[(0 * HID + jc) * HID + 2 * p],
                       0.5f * w_hh[(0 * HID + jc) * HID + 2 * p + 1]);
        wf2[p] = pack2(0.5f * w_hh[(1 * HID + jc) * HID + 2 * p],
                       0.5f * w_hh[(1 * HID + jc) * HID + 2 * p + 1]);
        wg2[p] = pack2(       w_hh[(2 * HID + jc) * HID + 2 * p],
                              w_hh[(2 * HID + jc) * HID + 2 * p + 1]);
        wo2[p] = pack2(0.5f * w_hh[(3 * HID + jc) * HID + 2 * p],
                       0.5f * w_hh[(3 * HID + jc) * HID + 2 * p + 1]);
    }
    // Input weight + bias packed into (value, 0): seeded via one FFMA2 each.
    u64 wxi2 = pack2(0.5f * w_ih[0 * HID + jc], 0.0f);
    u64 wxf2 = pack2(0.5f * w_ih[1 * HID + jc], 0.0f);
    u64 wxg2 = pack2(       w_ih[2 * HID + jc], 0.0f);
    u64 wxo2 = pack2(0.5f * w_ih[3 * HID + jc], 0.0f);
    u64 bbi2 = pack2(0.5f * (b_ih[0 * HID + jc] + b_hh[0 * HID + jc]), 0.0f);
    u64 bbf2 = pack2(0.5f * (b_ih[1 * HID + jc] + b_hh[1 * HID + jc]), 0.0f);
    u64 bbg2 = pack2(       (b_ih[2 * HID + jc] + b_hh[2 * HID + jc]), 0.0f);
    u64 bbo2 = pack2(0.5f * (b_ih[3 * HID + jc] + b_hh[3 * HID + jc]), 0.0f);

    float cst = 0.0f;
    float hcst = 0.0f;                  // 0.5 * cst, maintained each step

    // Seed h = 0 in smem.
    sts_f32(smy, 0.0f);

    const float* xrow = x + (size_t)grp * LSEQ;

    // Load chunk 0 raw (12 floats) and compute its 4 conv outputs.
    float4 A = *reinterpret_cast<const float4*>(xrow);
    float4 M = *reinterpret_cast<const float4*>(xrow + 4);
    float4 C = *reinterpret_cast<const float4*>(xrow + 8);

    float cts[4];
    {
        float o0 = fmaf(A.x, cw0, fmaf(A.y, cw1, fmaf(A.z, cw2, cb0)));
        float o1 = fmaf(A.w, cw0, fmaf(M.x, cw1, fmaf(M.y, cw2, cb0)));
        float o2 = fmaf(M.z, cw0, fmaf(M.w, cw1, fmaf(C.x, cw2, cb0)));
        float o3 = fmaf(C.y, cw0, fmaf(C.z, cw1, fmaf(C.w, cw2, cb0)));
        cts[0] = fmaxf(o0, 0.0f);
        cts[1] = fmaxf(o1, 0.0f);
        cts[2] = fmaxf(o2, 0.0f);
        cts[3] = fmaxf(o3, 0.0f);
    }

    for (int t4 = 0; t4 < LP / 4; t4++) {
        // Prefetch next chunk's raw input (clamped on the last iteration to
        // stay in bounds; its conv result is then unused).
        int nidx = t4 + 1 < LP / 4 ? t4 + 1 : t4;
        const float* np = xrow + 12 * nidx;
        A = *reinterpret_cast<const float4*>(np);
        M = *reinterpret_cast<const float4*>(np + 4);
        C = *reinterpret_cast<const float4*>(np + 8);

#pragma unroll
        for (int u = 0; u < 4; u++) {
            u64 ct2 = dup2(cts[u]);     // off critical path (ct known early)

            // Broadcast previous h as packed pairs (smem broadcast reads).
            u64 h01, h23, h45, h67, h89;
            lds_v2u64(sbase, h01, h23);
            lds_v2u64(sbase + 16u, h45, h67);
            h89 = lds_u64(sbase + 32u);

            // Seeds (independent of h; scheduled into the LDS shadow).
            u64 ag2 = ffma2(wxg2, ct2, bbg2);
            u64 ai2 = ffma2(wxi2, ct2, bbi2);
            u64 af2 = ffma2(wxf2, ct2, bbf2);
            u64 ao2 = ffma2(wxo2, ct2, bbo2);

            ag2 = ffma2(wg2[0], h01, ag2);
            ai2 = ffma2(wi2[0], h01, ai2);
            af2 = ffma2(wf2[0], h01, af2);
            ao2 = ffma2(wo2[0], h01, ao2);
            ag2 = ffma2(wg2[1], h23, ag2);
            ai2 = ffma2(wi2[1], h23, ai2);
            af2 = ffma2(wf2[1], h23, af2);
            ao2 = ffma2(wo2[1], h23, ao2);
            ag2 = ffma2(wg2[2], h45, ag2);
            ai2 = ffma2(wi2[2], h45, ai2);
            af2 = ffma2(wf2[2], h45, af2);
            ao2 = ffma2(wo2[2], h45, ao2);
            ag2 = ffma2(wg2[3], h67, ag2);
            ai2 = ffma2(wi2[3], h67, ai2);
            af2 = ffma2(wf2[3], h67, af2);
            ao2 = ffma2(wo2[3], h67, ao2);
            ag2 = ffma2(wg2[4], h89, ag2);
            ai2 = ffma2(wi2[4], h89, ai2);
            af2 = ffma2(wf2[4], h89, af2);
            ao2 = ffma2(wo2[4], h89, ao2);

            float ag = hsum2(ag2);
            float ai = hsum2(ai2);
            float af = hsum2(af2);
            float ao = hsum2(ao2);

            // Activations (MUFU issue order = consumption order).
            float gg = tanh_apx(ag);    // tanh gate
            float ti = tanh_apx(ai);    // tanh(0.5*preact_i)
            float tf = tanh_apx(af);
            float to = tanh_apx(ao);

            // c' = sig(f)*c + sig(i)*g with sig(x)=0.5*t+0.5 folded:
            //   P = 0.5*gg*ti + 0.5*gg ; Q = 0.5*c + P ; c' = fma(0.5*c, tf, Q)
            float hgg = 0.5f * gg;
            float P = fmaf(hgg, ti, hgg);
            float Q = hcst + P;
            cst = fmaf(hcst, tf, Q);
            hcst = 0.5f * cst;

            float og = fmaf(to, 0.5f, 0.5f);
            float h = og * tanh_apx(cst);

            // Publish new h for the next step.
            sts_f32(smy, h);
        }

        // Conv for the prefetched chunk (identical expression order to the
        // original conv kernel -> bit-identical cts).
        {
            float o0 = fmaf(A.x, cw0, fmaf(A.y, cw1, fmaf(A.z, cw2, cb0)));
            float o1 = fmaf(A.w, cw0, fmaf(M.x, cw1, fmaf(M.y, cw2, cb0)));
            float o2 = fmaf(M.z, cw0, fmaf(M.w, cw1, fmaf(C.x, cw2, cb0)));
            float o3 = fmaf(C.y, cw0, fmaf(C.z, cw1, fmaf(C.w, cw2, cb0)));
            cts[0] = fmaxf(o0, 0.0f);
            cts[1] = fmaxf(o1, 0.0f);
            cts[2] = fmaxf(o2, 0.0f);
            cts[3] = fmaxf(o3, 0.0f);
        }
    }

    // Final MLP: read h_0..h_9 from smem; lanes 0..2 emit the 3 outputs.
    if (j < 3) {
        float h0, h1, h2, h3, h4, h5, h6, h7, h8, h9;
        lds_v2f(sbase,       h0, h1);
        lds_v2f(sbase + 8u,  h2, h3);
        lds_v2f(sbase + 16u, h4, h5);
        lds_v2f(sbase + 24u, h6, h7);
        lds_v2f(sbase + 32u, h8, h9);
        const float* mw = mlp_w + j * HID;
        float acc = mlp_b[j];
        acc = fmaf(mw[0], h0, acc);
        acc = fmaf(mw[1], h1, acc);
        acc = fmaf(mw[2], h2, acc);
        acc = fmaf(mw[3], h3, acc);
        acc = fmaf(mw[4], h4, acc);
        acc = fmaf(mw[5], h5, acc);
        acc = fmaf(mw[6], h6, acc);
        acc = fmaf(mw[7], h7, acc);
        acc = fmaf(mw[8], h8, acc);
        acc = fmaf(mw[9], h9, acc);
        out[grp * 3 + j] = acc;
    }
}

// ---------------------------------------------------------------------------
extern "C" void kernel_launch(void* const* d_in, const int* in_sizes, int n_in,
                              void* d_out, int out_size) {
    const float* x      = (const float*)d_in[0];
    const float* conv_w = (const float*)d_in[1];
    const float* conv_b = (const float*)d_in[2];
    const float* w_ih   = (const float*)d_in[3];
    const float* w_hh   = (const float*)d_in[4];
    const float* b_ih   = (const float*)d_in[5];
    const float* b_hh   = (const float*)d_in[6];
    const float* mlp_w  = (const float*)d_in[7];
    const float* mlp_b  = (const float*)d_in[8];
    float* out = (float*)d_out;

    // Single fused kernel: 512 groups * 16 lanes = 8192 threads (64 x 128).
    int threads = 128;
    int blocks = (BATCH * 16) / threads;   // 64
    lstm_kernel<<<blocks, threads>>>(x, conv_w, conv_b, w_ih, w_hh,
                                     b_ih, b_hh, mlp_w, mlp_b, out);
}

// round 10
// speedup vs baseline: 1.0741x; 1.0018x over previous
#include <cuda_runtime.h>

// Problem constants (fixed by the reference).
#define BATCH 512
#define LSEQ  24576
#define LP    8192        // LSEQ / 3
#define HID   10

// ---------------------------------------------------------------------------
// Packed f32x2 + MUFU helpers.
// ---------------------------------------------------------------------------
typedef unsigned long long u64;

__device__ __forceinline__ u64 dup2(float x) {
    u64 r;
    asm("mov.b64 %0, {%1, %1};" : "=l"(r) : "f"(x));
    return r;
}
__device__ __forceinline__ u64 pack2(float lo, float hi) {
    u64 r;
    asm("mov.b64 %0, {%1, %2};" : "=l"(r) : "f"(lo), "f"(hi));
    return r;
}
__device__ __forceinline__ u64 ffma2(u64 a, u64 b, u64 c) {
    u64 d;
    asm("fma.rn.f32x2 %0, %1, %2, %3;" : "=l"(d) : "l"(a), "l"(b), "l"(c));
    return d;
}
__device__ __forceinline__ u64 mul2(u64 a, u64 b) {
    u64 d;
    asm("mul.rn.f32x2 %0, %1, %2;" : "=l"(d) : "l"(a), "l"(b));
    return d;
}
__device__ __forceinline__ u64 add2f(u64 a, u64 b) {
    u64 d;
    asm("add.rn.f32x2 %0, %1, %2;" : "=l"(d) : "l"(a), "l"(b));
    return d;
}
__device__ __forceinline__ float hsum2(u64 v) {
    float lo, hi;
    asm("mov.b64 {%0, %1}, %2;" : "=f"(lo), "=f"(hi) : "l"(v));
    return lo + hi;
}
__device__ __forceinline__ float tanh_apx(float x) {
    float y;
    asm("tanh.approx.f32 %0, %1;" : "=f"(y) : "f"(x));
    return y;
}

// Shared-memory broadcast helpers: h vector read back as packed 64-bit pairs.
__device__ __forceinline__ void sts_f32(unsigned addr, float v) {
    asm volatile("st.shared.f32 [%0], %1;" :: "r"(addr), "f"(v) : "memory");
}
__device__ __forceinline__ void lds_v2u64(unsigned addr, u64& a, u64& b) {
    asm volatile("ld.shared.v2.u64 {%0,%1}, [%2];"
                 : "=l"(a), "=l"(b) : "r"(addr) : "memory");
}
__device__ __forceinline__ u64 lds_u64(unsigned addr) {
    u64 a;
    asm volatile("ld.shared.u64 %0, [%1];" : "=l"(a) : "r"(addr) : "memory");
    return a;
}
__device__ __forceinline__ void lds_v2f(unsigned addr, float& a, float& b) {
    asm volatile("ld.shared.v2.f32 {%0,%1}, [%2];"
                 : "=f"(a), "=f"(b) : "r"(addr) : "memory");
}

// ---------------------------------------------------------------------------
// Fused kernel: conv1d(k=3,s=3)+relu computed inline (latency shadow, one
// chunk ahead) + LSTM scan + final MLP.
// Lane j<10 of a 16-lane segment owns hidden unit j. Gate dots via FFMA2 over
// k-pairs in TWO parallel chains (depth 2 seeded, depth 3) combined by add2:
// preact depth after h = 16 instead of 20. 4-step unroll keeps the hot body
// inside the ~6KB L0 I-cache (the 8-unroll variant thrashed it).
// ---------------------------------------------------------------------------
__global__ void __launch_bounds__(128, 1)
lstm_kernel(const float* __restrict__ x,
            const float* __restrict__ cw,
            const float* __restrict__ cb,
            const float* __restrict__ w_ih,
            const float* __restrict__ w_hh,
            const float* __restrict__ b_ih,
            const float* __restrict__ b_hh,
            const float* __restrict__ mlp_w,
            const float* __restrict__ mlp_b,
            float* __restrict__ out) {
    __shared__ __align__(16) float hbuf[8 * 16];   // 8 segments * 16 slots

    int tid = blockIdx.x * blockDim.x + threadIdx.x;
    int grp = tid >> 4;                 // batch element, 0..511
    int j   = tid & 15;                 // lane within segment
    int jc  = j < HID ? j : HID - 1;    // clamp idle lanes onto valid rows
    if (grp >= BATCH) return;

    int seg = (threadIdx.x >> 4);       // segment within block, 0..7
    unsigned sbase = (unsigned)__cvta_generic_to_shared(&hbuf[seg * 16]);
    unsigned smy   = sbase + 4u * (unsigned)j;

    // Conv weights.
    float cw0 = cw[0], cw1 = cw[1], cw2 = cw[2], cb0 = cb[0];

    // Recurrent weights packed over k-pairs (torch gate order i,f,g,o).
    // Sigmoid-gate weights pre-scaled by 0.5 (sigmoid via tanh identity).
    u64 wi2[5], wf2[5], wg2[5], wo2[5];
#pragma unroll
    for (int p = 0; p < 5; p++) {
        wi2[p] = pack2(0.5f * w_hh[(0 * HID + jc) * HID + 2 * p],
                       0.5f * w_hh[(0 * HID + jc) * HID + 2 * p + 1]);
        wf2[p] = pack2(0.5f * w_hh[(1 * HID + jc) * HID + 2 * p],
                       0.5f * w_hh[(1 * HID + jc) * HID + 2 * p + 1]);
        wg2[p] = pack2(       w_hh[(2 * HID + jc) * HID + 2 * p],
                              w_hh[(2 * HID + jc) * HID + 2 * p + 1]);
        wo2[p] = pack2(0.5f * w_hh[(3 * HID + jc) * HID + 2 * p],
                       0.5f * w_hh[(3 * HID + jc) * HID + 2 * p + 1]);
    }
    // Input weight + bias packed into (value, 0): seeded via one FFMA2 each.
    u64 wxi2 = pack2(0.5f * w_ih[0 * HID + jc], 0.0f);
    u64 wxf2 = pack2(0.5f * w_ih[1 * HID + jc], 0.0f);
    u64 wxg2 = pack2(       w_ih[2 * HID + jc], 0.0f);
    u64 wxo2 = pack2(0.5f * w_ih[3 * HID + jc], 0.0f);
    u64 bbi2 = pack2(0.5f * (b_ih[0 * HID + jc] + b_hh[0 * HID + jc]), 0.0f);
    u64 bbf2 = pack2(0.5f * (b_ih[1 * HID + jc] + b_hh[1 * HID + jc]), 0.0f);
    u64 bbg2 = pack2(       (b_ih[2 * HID + jc] + b_hh[2 * HID + jc]), 0.0f);
    u64 bbo2 = pack2(0.5f * (b_ih[3 * HID + jc] + b_hh[3 * HID + jc]), 0.0f);

    float cst = 0.0f;
    float hcst = 0.0f;                  // 0.5 * cst, maintained each step

    // Seed h = 0 in smem.
    sts_f32(smy, 0.0f);

    const float* xrow = x + (size_t)grp * LSEQ;

    // Load chunk 0 raw (12 floats) and compute its 4 conv outputs.
    float4 A = *reinterpret_cast<const float4*>(xrow);
    float4 M = *reinterpret_cast<const float4*>(xrow + 4);
    float4 C = *reinterpret_cast<const float4*>(xrow + 8);

    float cts[4];
    {
        float o0 = fmaf(A.x, cw0, fmaf(A.y, cw1, fmaf(A.z, cw2, cb0)));
        float o1 = fmaf(A.w, cw0, fmaf(M.x, cw1, fmaf(M.y, cw2, cb0)));
        float o2 = fmaf(M.z, cw0, fmaf(M.w, cw1, fmaf(C.x, cw2, cb0)));
        float o3 = fmaf(C.y, cw0, fmaf(C.z, cw1, fmaf(C.w, cw2, cb0)));
        cts[0] = fmaxf(o0, 0.0f);
        cts[1] = fmaxf(o1, 0.0f);
        cts[2] = fmaxf(o2, 0.0f);
        cts[3] = fmaxf(o3, 0.0f);
    }

    for (int t4 = 0; t4 < LP / 4; t4++) {
        // Prefetch next chunk's raw input (clamped on the last iteration).
        int nidx = t4 + 1 < LP / 4 ? t4 + 1 : t4;
        const float* np = xrow + 12 * nidx;
        A = *reinterpret_cast<const float4*>(np);
        M = *reinterpret_cast<const float4*>(np + 4);
        C = *reinterpret_cast<const float4*>(np + 8);

#pragma unroll
        for (int u = 0; u < 4; u++) {
            u64 ct2 = dup2(cts[u]);     // off critical path (ct known early)

            // Broadcast previous h as packed pairs (smem broadcast reads).
            u64 h01, h23, h45, h67, h89;
            lds_v2u64(sbase, h01, h23);
            lds_v2u64(sbase + 16u, h45, h67);
            h89 = lds_u64(sbase + 32u);

            // Seeds (independent of h; scheduled into the LDS shadow).
            u64 sg = ffma2(wxg2, ct2, bbg2);
            u64 si = ffma2(wxi2, ct2, bbi2);
            u64 sf = ffma2(wxf2, ct2, bbf2);
            u64 so = ffma2(wxo2, ct2, bbo2);

            // Chain A (depth 2 after h): seed + h01 + h23.
            u64 gA = ffma2(wg2[0], h01, sg);
            u64 iA = ffma2(wi2[0], h01, si);
            u64 fA = ffma2(wf2[0], h01, sf);
            u64 oA = ffma2(wo2[0], h01, so);
            gA = ffma2(wg2[1], h23, gA);
            iA = ffma2(wi2[1], h23, iA);
            fA = ffma2(wf2[1], h23, fA);
            oA = ffma2(wo2[1], h23, oA);

            // Chain B (depth 3 after h): w45*h45 + h67 + h89.
            u64 gB = mul2(wg2[2], h45);
            u64 iB = mul2(wi2[2], h45);
            u64 fB = mul2(wf2[2], h45);
            u64 oB = mul2(wo2[2], h45);
            gB = ffma2(wg2[3], h67, gB);
            iB = ffma2(wi2[3], h67, iB);
            fB = ffma2(wf2[3], h67, fB);
            oB = ffma2(wo2[3], h67, oB);
            gB = ffma2(wg2[4], h89, gB);
            iB = ffma2(wi2[4], h89, iB);
            fB = ffma2(wf2[4], h89, fB);
            oB = ffma2(wo2[4], h89, oB);

            float ag = hsum2(add2f(gA, gB));
            float ai = hsum2(add2f(iA, iB));
            float af = hsum2(add2f(fA, fB));
            float ao = hsum2(add2f(oA, oB));

            // Activations (MUFU issue order = consumption order: g, i, f, o).
            float gg = tanh_apx(ag);    // tanh gate
            float ti = tanh_apx(ai);    // tanh(0.5*preact_i)
            float tf = tanh_apx(af);
            float to = tanh_apx(ao);

            // c' = sig(f)*c + sig(i)*g with sig(x)=0.5*t+0.5 folded:
            //   P = 0.5*gg*ti + 0.5*gg ; Q = 0.5*c + P ; c' = fma(0.5*c, tf, Q)
            float hgg = 0.5f * gg;
            float P = fmaf(hgg, ti, hgg);
            float Q = hcst + P;
            cst = fmaf(hcst, tf, Q);
            hcst = 0.5f * cst;

            float og = fmaf(to, 0.5f, 0.5f);
            float h = og * tanh_apx(cst);

            // Publish new h for the next step.
            sts_f32(smy, h);
        }

        // Conv for the prefetched chunk (identical expression order to the
        // reference conv -> bit-identical cts).
        {
            float o0 = fmaf(A.x, cw0, fmaf(A.y, cw1, fmaf(A.z, cw2, cb0)));
            float o1 = fmaf(A.w, cw0, fmaf(M.x, cw1, fmaf(M.y, cw2, cb0)));
            float o2 = fmaf(M.z, cw0, fmaf(M.w, cw1, fmaf(C.x, cw2, cb0)));
            float o3 = fmaf(C.y, cw0, fmaf(C.z, cw1, fmaf(C.w, cw2, cb0)));
            cts[0] = fmaxf(o0, 0.0f);
            cts[1] = fmaxf(o1, 0.0f);
            cts[2] = fmaxf(o2, 0.0f);
            cts[3] = fmaxf(o3, 0.0f);
        }
    }

    // Final MLP: read h_0..h_9 from smem; lanes 0..2 emit the 3 outputs.
    if (j < 3) {
        float h0, h1, h2, h3, h4, h5, h6, h7, h8, h9;
        lds_v2f(sbase,       h0, h1);
        lds_v2f(sbase + 8u,  h2, h3);
        lds_v2f(sbase + 16u, h4, h5);
        lds_v2f(sbase + 24u, h6, h7);
        lds_v2f(sbase + 32u, h8, h9);
        const float* mw = mlp_w + j * HID;
        float acc = mlp_b[j];
        acc = fmaf(mw[0], h0, acc);
        acc = fmaf(mw[1], h1, acc);
        acc = fmaf(mw[2], h2, acc);
        acc = fmaf(mw[3], h3, acc);
        acc = fmaf(mw[4], h4, acc);
        acc = fmaf(mw[5], h5, acc);
        acc = fmaf(mw[6], h6, acc);
        acc = fmaf(mw[7], h7, acc);
        acc = fmaf(mw[8], h8, acc);
        acc = fmaf(mw[9], h9, acc);
        out[grp * 3 + j] = acc;
    }
}

// ---------------------------------------------------------------------------
extern "C" void kernel_launch(void* const* d_in, const int* in_sizes, int n_in,
                              void* d_out, int out_size) {
    const float* x      = (const float*)d_in[0];
    const float* conv_w = (const float*)d_in[1];
    const float* conv_b = (const float*)d_in[2];
    const float* w_ih   = (const float*)d_in[3];
    const float* w_hh   = (const float*)d_in[4];
    const float* b_ih   = (const float*)d_in[5];
    const float* b_hh   = (const float*)d_in[6];
    const float* mlp_w  = (const float*)d_in[7];
    const float* mlp_b  = (const float*)d_in[8];
    float* out = (float*)d_out;

    // Single fused kernel: 512 groups * 16 lanes = 8192 threads (64 x 128).
    int threads = 128;
    int blocks = (BATCH * 16) / threads;   // 64
    lstm_kernel<<<blocks, threads>>>(x, conv_w, conv_b, w_ih, w_hh,
                                     b_ih, b_hh, mlp_w, mlp_b, out);
}

// round 11
// speedup vs baseline: 1.1581x; 1.0782x over previous
#include <cuda_runtime.h>

// Problem constants (fixed by the reference).
#define BATCH 512
#define LSEQ  24576
#define LP    8192        // LSEQ / 3
#define HID   10

// ---------------------------------------------------------------------------
// Packed f32x2 + MUFU helpers.
// ---------------------------------------------------------------------------
typedef unsigned long long u64;

__device__ __forceinline__ u64 dup2(float x) {
    u64 r;
    asm("mov.b64 %0, {%1, %1};" : "=l"(r) : "f"(x));
    return r;
}
__device__ __forceinline__ u64 pack2(float lo, float hi) {
    u64 r;
    asm("mov.b64 %0, {%1, %2};" : "=l"(r) : "f"(lo), "f"(hi));
    return r;
}
__device__ __forceinline__ u64 ffma2(u64 a, u64 b, u64 c) {
    u64 d;
    asm("fma.rn.f32x2 %0, %1, %2, %3;" : "=l"(d) : "l"(a), "l"(b), "l"(c));
    return d;
}
__device__ __forceinline__ float hsum2(u64 v) {
    float lo, hi;
    asm("mov.b64 {%0, %1}, %2;" : "=f"(lo), "=f"(hi) : "l"(v));
    return lo + hi;
}
__device__ __forceinline__ float tanh_apx(float x) {
    float y;
    asm("tanh.approx.f32 %0, %1;" : "=f"(y) : "f"(x));
    return y;
}

// Shared-memory broadcast helpers: h vector read back as packed 64-bit pairs.
__device__ __forceinline__ void sts_f32(unsigned addr, float v) {
    asm volatile("st.shared.f32 [%0], %1;" :: "r"(addr), "f"(v) : "memory");
}
__device__ __forceinline__ void lds_v2u64(unsigned addr, u64& a, u64& b) {
    asm volatile("ld.shared.v2.u64 {%0,%1}, [%2];"
                 : "=l"(a), "=l"(b) : "r"(addr) : "memory");
}
__device__ __forceinline__ u64 lds_u64(unsigned addr) {
    u64 a;
    asm volatile("ld.shared.u64 %0, [%1];" : "=l"(a) : "r"(addr) : "memory");
    return a;
}
__device__ __forceinline__ void lds_v2f(unsigned addr, float& a, float& b) {
    asm volatile("ld.shared.v2.f32 {%0,%1}, [%2];"
                 : "=f"(a), "=f"(b) : "r"(addr) : "memory");
}

// ---------------------------------------------------------------------------
// Fused kernel: inline conv1d(k=3,s=3)+relu + LSTM scan + final MLP.
// ONE WARP (32 lanes) per batch element:
//   Half A (lanes 0-15):  lane j owns unit j; chains X=i, Y=g, Z=f;
//                         maintains cst, computes h, stores it.
//   Half B (lanes 16-31): chain X=o (Y,Z slots run don't-care data);
//                         computes og = sig(o) and ships it via shfl_xor(16).
// The shfl result is consumed only at the final h-mul (~45 cyc later), so its
// 26-cyc latency is fully hidden. Per-lane h-dependent fma ops: 18 vs 24.
// ---------------------------------------------------------------------------
__global__ void __launch_bounds__(128, 1)
lstm_kernel(const float* __restrict__ x,
            const float* __restrict__ cw,
            const float* __restrict__ cb,
            const float* __restrict__ w_ih,
            const float* __restrict__ w_hh,
            const float* __restrict__ b_ih,
            const float* __restrict__ b_hh,
            const float* __restrict__ mlp_w,
            const float* __restrict__ mlp_b,
            float* __restrict__ out) {
    __shared__ __align__(16) float hbuf[4 * 16];   // 4 warps/block * 16 slots

    int tid  = blockIdx.x * blockDim.x + threadIdx.x;
    int grp  = tid >> 5;                // batch element, 0..511
    int lane = tid & 31;
    int half = lane >> 4;               // 0 = A (i,g,f + cst), 1 = B (o)
    int j    = lane & 15;
    int jc   = j < HID ? j : HID - 1;   // clamp idle lanes onto valid rows
    if (grp >= BATCH) return;

    int seg = (threadIdx.x >> 5);       // warp within block, 0..3
    unsigned sbase = (unsigned)__cvta_generic_to_shared(&hbuf[seg * 16]);
    unsigned smy   = sbase + 4u * (unsigned)j;

    // Conv weights.
    float cw0 = cw[0], cw1 = cw[1], cw2 = cw[2], cb0 = cb[0];

    // Gate rows (torch order i,f,g,o):
    //   chain X: A -> i (row 0), B -> o (row 3); sigmoid, scale 0.5.
    //   chain Y: g (row 2), scale 1   (B's result is don't-care).
    //   chain Z: f (row 1), scale 0.5 (B's result is don't-care).
    int rX = half ? 3 : 0;

    u64 wX2[5], wY2[5], wZ2[5];
#pragma unroll
    for (int p = 0; p < 5; p++) {
        wX2[p] = pack2(0.5f * w_hh[(rX * HID + jc) * HID + 2 * p],
                       0.5f * w_hh[(rX * HID + jc) * HID + 2 * p + 1]);
        wY2[p] = pack2(       w_hh[(2 * HID + jc) * HID + 2 * p],
                              w_hh[(2 * HID + jc) * HID + 2 * p + 1]);
        wZ2[p] = pack2(0.5f * w_hh[(1 * HID + jc) * HID + 2 * p],
                       0.5f * w_hh[(1 * HID + jc) * HID + 2 * p + 1]);
    }
    u64 wxX2 = pack2(0.5f * w_ih[rX * HID + jc], 0.0f);
    u64 wxY2 = pack2(       w_ih[2 * HID + jc], 0.0f);
    u64 wxZ2 = pack2(0.5f * w_ih[1 * HID + jc], 0.0f);
    u64 bbX2 = pack2(0.5f * (b_ih[rX * HID + jc] + b_hh[rX * HID + jc]), 0.0f);
    u64 bbY2 = pack2(       (b_ih[2 * HID + jc] + b_hh[2 * HID + jc]), 0.0f);
    u64 bbZ2 = pack2(0.5f * (b_ih[1 * HID + jc] + b_hh[1 * HID + jc]), 0.0f);

    float cst = 0.0f;
    float hcst = 0.0f;                  // 0.5 * cst (A); don't-care in B
    bool isA = (half == 0);

    // Seed h = 0 in smem (half A owns the slots).
    if (isA) sts_f32(smy, 0.0f);
    __syncwarp();

    const float* xrow = x + (size_t)grp * LSEQ;

    // Load chunk 0 raw (12 floats) and compute its 4 conv outputs.
    float4 A4 = *reinterpret_cast<const float4*>(xrow);
    float4 M4 = *reinterpret_cast<const float4*>(xrow + 4);
    float4 C4 = *reinterpret_cast<const float4*>(xrow + 8);

    float cts[4];
    {
        float o0 = fmaf(A4.x, cw0, fmaf(A4.y, cw1, fmaf(A4.z, cw2, cb0)));
        float o1 = fmaf(A4.w, cw0, fmaf(M4.x, cw1, fmaf(M4.y, cw2, cb0)));
        float o2 = fmaf(M4.z, cw0, fmaf(M4.w, cw1, fmaf(C4.x, cw2, cb0)));
        float o3 = fmaf(C4.y, cw0, fmaf(C4.z, cw1, fmaf(C4.w, cw2, cb0)));
        cts[0] = fmaxf(o0, 0.0f);
        cts[1] = fmaxf(o1, 0.0f);
        cts[2] = fmaxf(o2, 0.0f);
        cts[3] = fmaxf(o3, 0.0f);
    }

    for (int t4 = 0; t4 < LP / 4; t4++) {
        // Prefetch next chunk's raw input (clamped on the last iteration).
        int nidx = t4 + 1 < LP / 4 ? t4 + 1 : t4;
        const float* np = xrow + 12 * nidx;
        A4 = *reinterpret_cast<const float4*>(np);
        M4 = *reinterpret_cast<const float4*>(np + 4);
        C4 = *reinterpret_cast<const float4*>(np + 8);

#pragma unroll
        for (int u = 0; u < 4; u++) {
            u64 ct2 = dup2(cts[u]);     // off critical path (ct known early)

            // Broadcast previous h as packed pairs (smem broadcast reads).
            u64 h01, h23, h45, h67, h89;
            lds_v2u64(sbase, h01, h23);
            lds_v2u64(sbase + 16u, h45, h67);
            h89 = lds_u64(sbase + 32u);

            // Seeds (independent of h; scheduled into the LDS shadow).
            u64 aX = ffma2(wxX2, ct2, bbX2);
            u64 aY = ffma2(wxY2, ct2, bbY2);
            u64 aZ = ffma2(wxZ2, ct2, bbZ2);

            // Three 5-deep FFMA2 chains, interleaved.
            aX = ffma2(wX2[0], h01, aX);
            aY = ffma2(wY2[0], h01, aY);
            aZ = ffma2(wZ2[0], h01, aZ);
            aX = ffma2(wX2[1], h23, aX);
            aY = ffma2(wY2[1], h23, aY);
            aZ = ffma2(wZ2[1], h23, aZ);
            aX = ffma2(wX2[2], h45, aX);
            aY = ffma2(wY2[2], h45, aY);
            aZ = ffma2(wZ2[2], h45, aZ);
            aX = ffma2(wX2[3], h67, aX);
            aY = ffma2(wY2[3], h67, aY);
            aZ = ffma2(wZ2[3], h67, aZ);
            aX = ffma2(wX2[4], h89, aX);
            aY = ffma2(wY2[4], h89, aY);
            aZ = ffma2(wZ2[4], h89, aZ);

            // tX = A: tanh(0.5*pre_i) | B: tanh(0.5*pre_o)
            float tX = tanh_apx(hsum2(aX));
            float tY = tanh_apx(hsum2(aY));   // A: tanh(pre_g)
            float tZ = tanh_apx(hsum2(aZ));   // A: tanh(0.5*pre_f)

            // B forms og = sig(o) = 0.5*tX + 0.5; shfl ships it to A early
            // (consumed only at the final h-mul -> latency hidden).
            float og_loc = fmaf(tX, 0.5f, 0.5f);
            float og = __shfl_xor_sync(0xffffffffu, og_loc, 16, 32);

            // c-update (valid in A; bounded don't-care in B):
            //   P = 0.5*gg*ti + 0.5*gg ; Q = 0.5*c + P ; c' = fma(0.5*c, tf, Q)
            float hgg = 0.5f * tY;
            float P = fmaf(hgg, tX, hgg);
            float Q = hcst + P;
            cst = fmaf(hcst, tZ, Q);
            hcst = 0.5f * cst;

            float h = og * tanh_apx(cst);

            // Publish new h for the next step (half A owns the slots).
            if (isA) sts_f32(smy, h);
        }

        // Conv for the prefetched chunk (identical expression order to the
        // reference conv -> bit-identical cts).
        {
            float o0 = fmaf(A4.x, cw0, fmaf(A4.y, cw1, fmaf(A4.z, cw2, cb0)));
            float o1 = fmaf(A4.w, cw0, fmaf(M4.x, cw1, fmaf(M4.y, cw2, cb0)));
            float o2 = fmaf(M4.z, cw0, fmaf(M4.w, cw1, fmaf(C4.x, cw2, cb0)));
            float o3 = fmaf(C4.y, cw0, fmaf(C4.z, cw1, fmaf(C4.w, cw2, cb0)));
            cts[0] = fmaxf(o0, 0.0f);
            cts[1] = fmaxf(o1, 0.0f);
            cts[2] = fmaxf(o2, 0.0f);
            cts[3] = fmaxf(o3, 0.0f);
        }
    }

    // Final MLP: read h_0..h_9 from smem; lanes 0..2 emit the 3 outputs.
    __syncwarp();
    if (lane < 3) {
        float h0, h1, h2, h3, h4, h5, h6, h7, h8, h9;
        lds_v2f(sbase,       h0, h1);
        lds_v2f(sbase + 8u,  h2, h3);
        lds_v2f(sbase + 16u, h4, h5);
        lds_v2f(sbase + 24u, h6, h7);
        lds_v2f(sbase + 32u, h8, h9);
        const float* mw = mlp_w + lane * HID;
        float acc = mlp_b[lane];
        acc = fmaf(mw[0], h0, acc);
        acc = fmaf(mw[1], h1, acc);
        acc = fmaf(mw[2], h2, acc);
        acc = fmaf(mw[3], h3, acc);
        acc = fmaf(mw[4], h4, acc);
        acc = fmaf(mw[5], h5, acc);
        acc = fmaf(mw[6], h6, acc);
        acc = fmaf(mw[7], h7, acc);
        acc = fmaf(mw[8], h8, acc);
        acc = fmaf(mw[9], h9, acc);
        out[grp * 3 + lane] = acc;
    }
}

// ---------------------------------------------------------------------------
extern "C" void kernel_launch(void* const* d_in, const int* in_sizes, int n_in,
                              void* d_out, int out_size) {
    const float* x      = (const float*)d_in[0];
    const float* conv_w = (const float*)d_in[1];
    const float* conv_b = (const float*)d_in[2];
    const float* w_ih   = (const float*)d_in[3];
    const float* w_hh   = (const float*)d_in[4];
    const float* b_ih   = (const float*)d_in[5];
    const float* b_hh   = (const float*)d_in[6];
    const float* mlp_w  = (const float*)d_in[7];
    const float* mlp_b  = (const float*)d_in[8];
    float* out = (float*)d_out;

    // Single fused kernel: 512 batches * 32 lanes = 16384 threads (128 x 128).
    int threads = 128;
    int blocks = (BATCH * 32) / threads;   // 128
    lstm_kernel<<<blocks, threads>>>(x, conv_w, conv_b, w_ih, w_hh,
                                     b_ih, b_hh, mlp_w, mlp_b, out);
}